// round 13
// baseline (speedup 1.0000x reference)
#include <cuda_runtime.h>
#include <cuda_fp16.h>
#include <cstdint>

// DynamicFilter via PTX mma.sync m16n8k16 fp16 (f32 accum) + fused 9-tap epilogue.
// CTA=(h,b), 512 threads = 16 warps = 4 M-strips x 4 cb-quarters (8 cb tiles each).
// Each quarter: depth-3 cp.async W ring, prefetch distance 1 (race-free: buffer
// (ci+1)%3 written at iter ci was last read at iter ci-2, barrier ci-1 between).
// X row staged once as packed f16x2 k-pairs. W pre-permuted by wperm_kernel.

#define CN 256
#define HN 128
#define WN 128
#define HW (HN*WN)

#define XPROWB 544u                 // bytes per packed-X row (128 b32 + pad)
#define XPBYTES (128u*XPROWB)       // 69632
#define WROWB 160u                  // bytes per W n-row in a chunk
#define WCHUNKB (72u*WROWB)         // 11520 per k64 chunk
#define SMEM_TOTAL (XPBYTES + 12u*WCHUNKB)  // 69632 + 138240 = 207872

__device__ uint32_t g_wperm[32 * 4 * 72 * 40];   // [cb][cc][n][40 words]

#define CPA16(dst, src) \
    asm volatile("cp.async.cg.shared.global [%0], [%1], 16;" :: "r"(dst), "l"(src) : "memory")
#define CP_COMMIT() asm volatile("cp.async.commit_group;" ::: "memory")
#define CP_WAIT(n)  asm volatile("cp.async.wait_group %0;" :: "n"(n) : "memory")

__device__ __forceinline__ uint32_t smem_u32(const void* p){
    uint32_t a;
    asm("{ .reg .u64 t; cvta.to.shared.u64 t, %1; cvt.u32.u64 %0, t; }" : "=r"(a) : "l"(p));
    return a;
}

__device__ __forceinline__ uint32_t pack_h2(float lo, float hi){
    uint32_t d;
    asm("cvt.rn.f16x2.f32 %0, %1, %2;" : "=r"(d) : "f"(hi), "f"(lo));
    return d;
}

__device__ __forceinline__ void mma16(float* c, const uint32_t* a, uint32_t b0, uint32_t b1){
    asm volatile(
        "mma.sync.aligned.m16n8k16.row.col.f32.f16.f16.f32 "
        "{%0,%1,%2,%3}, {%4,%5,%6,%7}, {%8,%9}, {%0,%1,%2,%3};"
        : "+f"(c[0]), "+f"(c[1]), "+f"(c[2]), "+f"(c[3])
        : "r"(a[0]), "r"(a[1]), "r"(a[2]), "r"(a[3]), "r"(b0), "r"(b1));
}

// ---- pre-kernel: permute + fp16-pack W (layout unchanged from R11) ----
__global__ void wperm_kernel(const float* __restrict__ Wm){
    int idx = blockIdx.x * 256 + threadIdx.x;        // 2304 * 128 total
    if (idx >= 2304 * 128) return;
    int row = idx >> 7, kp = idx & 127;
    int cb = row / 72, r = row % 72;
    int ch = r / 9, p = r % 9;
    int n  = 8 * p + ch;
    int cc = kp >> 5, kpl = kp & 31;
    int s = kpl >> 3, kp8 = kpl & 7;
    int col = 2 * (kp8 & 3) + (kp8 >> 2);
    float e = Wm[row * 256 + 2 * kp];
    float o = Wm[row * 256 + 2 * kp + 1];
    g_wperm[((size_t)(cb * 4 + cc) * 72 + n) * 40 + s * 8 + col] = pack_h2(e, o);
}

extern __shared__ float smf[];

__device__ __forceinline__ void stage_wq(int chunk, uint32_t wd, int tidq){
    const uint32_t* wsrc = g_wperm + (size_t)chunk * (72 * 40);
    #pragma unroll
    for (int i = 0; i < 6; ++i) {
        int slot = tidq + 128 * i;                   // 720 x 16B
        if (slot < 720) CPA16(wd + slot * 16, (const void*)(wsrc + slot * 4));
    }
    CP_COMMIT();
}

__global__ __launch_bounds__(512, 1)
void dynf_mma(const float* __restrict__ x, const float* __restrict__ bias,
              float* __restrict__ out)
{
    const uint32_t sx = smem_u32(smf);

    const int tid  = threadIdx.x;
    const int wid  = tid >> 5;
    const int lane = tid & 31;
    const int g = lane >> 2, q = lane & 3;
    const int quarter = wid >> 2;                    // 0..3: cb tiles [8q, 8q+8)
    const int tidq = tid & 127;
    const int wb   = (wid & 3) * 32;                 // warp's 32-row M strip
    const int h  = blockIdx.x;
    const int bb = blockIdx.y;

    const uint32_t swq = sx + XPBYTES + (uint32_t)quarter * (3u * WCHUNKB);

    // prefetch my quarter's chunk 0 into ring slot 0
    stage_wq(quarter * 32 + 0, swq + 0u * WCHUNKB, tidq);

    // stage X row as packed f16x2 pairs (all 512 threads, plain ld/st)
    {
        const float* xsrc = x + (size_t)bb * CN * HW + (size_t)h * WN;
        #pragma unroll 4
        for (int i = 0; i < 8; ++i) {
            int slot = tid + 512 * i;                // 4096: kp(128) x w4(32)
            int kp = slot >> 5, w4 = slot & 31;
            const float4 e = *(const float4*)(xsrc + (size_t)(2 * kp) * HW + w4 * 4);
            const float4 o = *(const float4*)(xsrc + (size_t)(2 * kp + 1) * HW + w4 * 4);
            uint32_t v0 = pack_h2(e.x, o.x), v1 = pack_h2(e.y, o.y);
            uint32_t v2 = pack_h2(e.z, o.z), v3 = pack_h2(e.w, o.w);
            asm volatile("st.shared.v4.b32 [%0], {%1,%2,%3,%4};"
                         :: "r"(sx + (uint32_t)kp * XPROWB + (uint32_t)w4 * 16),
                            "r"(v0), "r"(v1), "r"(v2), "r"(v3) : "memory");
        }
    }
    __syncthreads();                                 // X visible to all quarters

    // ===== per-quarter main loop: 8 cb tiles x 4 k64 chunks x 4 k16 steps =====
    int cur = 0;                                     // ring slot of current chunk
    for (int cbl = 0; cbl < 8; ++cbl) {
        const int cb = quarter * 8 + cbl;
        float acc[9][2][4];
        #pragma unroll
        for (int j = 0; j < 9; ++j)
            #pragma unroll
            for (int sA = 0; sA < 2; ++sA)
                #pragma unroll
                for (int e = 0; e < 4; ++e) acc[j][sA][e] = 0.f;

        for (int cc = 0; cc < 4; ++cc) {
            const int ci = cbl * 4 + cc;             // 0..31 within quarter
            const int nxt = (cur == 2) ? 0 : cur + 1;
            if (ci + 1 < 32) {
                // slot nxt was last read at iter ci-2; barrier at ci-1 separates.
                stage_wq(quarter * 32 + ci + 1, swq + (uint32_t)nxt * WCHUNKB, tidq);
                CP_WAIT(1);                          // chunk ci complete
            } else {
                CP_WAIT(0);
            }
            asm volatile("bar.sync %0, 128;" :: "r"(quarter + 1) : "memory");

            const uint32_t wbf = swq + (uint32_t)cur * WCHUNKB;
            #pragma unroll
            for (int s = 0; s < 4; ++s) {            // k16 steps
                const uint32_t r0 = sx + (uint32_t)(cc * 32 + s * 8 + q) * XPROWB
                                  + (uint32_t)(wb + g) * 4;
                uint32_t a0[4], a1[4];
                asm volatile("ld.shared.b32 %0, [%1];"      : "=r"(a0[0]) : "r"(r0));
                asm volatile("ld.shared.b32 %0, [%1+32];"   : "=r"(a0[1]) : "r"(r0));
                asm volatile("ld.shared.b32 %0, [%1+2176];" : "=r"(a0[2]) : "r"(r0));
                asm volatile("ld.shared.b32 %0, [%1+2208];" : "=r"(a0[3]) : "r"(r0));
                asm volatile("ld.shared.b32 %0, [%1+64];"   : "=r"(a1[0]) : "r"(r0));
                asm volatile("ld.shared.b32 %0, [%1+96];"   : "=r"(a1[1]) : "r"(r0));
                asm volatile("ld.shared.b32 %0, [%1+2240];" : "=r"(a1[2]) : "r"(r0));
                asm volatile("ld.shared.b32 %0, [%1+2272];" : "=r"(a1[3]) : "r"(r0));
                #pragma unroll
                for (int j = 0; j < 9; ++j) {
                    uint32_t b0, b1;
                    const uint32_t baddr = wbf + (uint32_t)(8 * j + g) * WROWB
                                         + (uint32_t)(s * 32 + q * 8);
                    asm volatile("ld.shared.v2.b32 {%0,%1}, [%2];"
                                 : "=r"(b0), "=r"(b1) : "r"(baddr));
                    mma16(acc[j][0], a0, b0, b1);
                    mma16(acc[j][1], a1, b0, b1);
                }
            }
            cur = nxt;
        }

        // ---- fused 9-tap epilogue: lane (g,q) owns ch 2q,2q+1 at 4 w positions ----
        #pragma unroll
        for (int b2 = 0; b2 < 2; ++b2) {
            const int ch = 2 * q + b2;
            const int c  = cb * 8 + ch;
            const float* xc = x + (size_t)(bb * CN + c) * HW;
            const float* bp = bias + cb * 72 + ch * 9;
            float res[4] = {0.f, 0.f, 0.f, 0.f};
            const int wpos[4] = { wb + g, wb + g + 8, wb + 16 + g, wb + 24 + g };
            #pragma unroll
            for (int j = 0; j < 9; ++j) {
                const int di = j / 3 - 1, dj = j % 3 - 1;
                const int hh = h + di;
                const bool hok = (hh >= 0) && (hh < HN);
                const float bv = __ldg(bp + j);
                const float* xr = xc + (size_t)hh * WN;
                const float fv[4] = { acc[j][0][b2], acc[j][0][2 + b2],
                                      acc[j][1][b2], acc[j][1][2 + b2] };
                #pragma unroll
                for (int r = 0; r < 4; ++r) {
                    const int ww = wpos[r] + dj;
                    const float xv = (hok && ww >= 0 && ww < WN) ? __ldg(xr + ww) : 0.f;
                    res[r] += (fv[r] + bv) * xv;
                }
            }
            float* orow = out + (size_t)(bb * CN + c) * HW + (size_t)h * WN;
            #pragma unroll
            for (int r = 0; r < 4; ++r) orow[wpos[r]] = res[r];
        }
    }
}

extern "C" void kernel_launch(void* const* d_in, const int* in_sizes, int n_in,
                              void* d_out, int out_size)
{
    const float* x = nullptr; const float* Wm = nullptr; const float* b = nullptr;
    for (int i = 0; i < n_in; ++i) {
        if      (in_sizes[i] == 16777216) x  = (const float*)d_in[i];
        else if (in_sizes[i] == 589824)   Wm = (const float*)d_in[i];
        else if (in_sizes[i] == 2304)     b  = (const float*)d_in[i];
    }
    float* out = (float*)d_out;

    wperm_kernel<<<1152, 256>>>(Wm);

    static int cfg_done = 0;
    if (!cfg_done) {
        cudaFuncSetAttribute(dynf_mma, cudaFuncAttributeMaxDynamicSharedMemorySize,
                             (int)SMEM_TOTAL);
        cfg_done = 1;
    }
    dim3 grid(HN, 4);                 // 512 CTAs: one per (h, b)
    dynf_mma<<<grid, 512, SMEM_TOTAL>>>(x, b, out);
}

// round 14
// speedup vs baseline: 1.0263x; 1.0263x over previous
#include <cuda_runtime.h>
#include <cuda_fp16.h>
#include <cstdint>

// DynamicFilter via PTX mma.sync m16n8k16 fp16 (f32 accum) + fused 9-tap epilogue.
// CTA=(h,b), 256 threads = 8 warps = 2 M-halves (M=64/warp, 4 m16 strips) x
// 4 cb-quarters (8 cb tiles each). One B ld.v2 feeds 4 mma. Each quarter
// (2 warps): depth-3 cp.async W ring, prefetch distance 1, 64-thread barrier.
// X row staged once as packed f16x2 k-pairs. W pre-permuted by wperm_kernel.

#define CN 256
#define HN 128
#define WN 128
#define HW (HN*WN)

#define XPROWB 544u                 // bytes per packed-X row (128 b32 + pad)
#define XPBYTES (128u*XPROWB)       // 69632
#define WROWB 160u                  // bytes per W n-row in a chunk
#define WCHUNKB (72u*WROWB)         // 11520 per k64 chunk
#define SMEM_TOTAL (XPBYTES + 12u*WCHUNKB)  // 69632 + 138240 = 207872

__device__ uint32_t g_wperm[32 * 4 * 72 * 40];   // [cb][cc][n][40 words]

#define CPA16(dst, src) \
    asm volatile("cp.async.cg.shared.global [%0], [%1], 16;" :: "r"(dst), "l"(src) : "memory")
#define CP_COMMIT() asm volatile("cp.async.commit_group;" ::: "memory")
#define CP_WAIT(n)  asm volatile("cp.async.wait_group %0;" :: "n"(n) : "memory")

__device__ __forceinline__ uint32_t smem_u32(const void* p){
    uint32_t a;
    asm("{ .reg .u64 t; cvta.to.shared.u64 t, %1; cvt.u32.u64 %0, t; }" : "=r"(a) : "l"(p));
    return a;
}

__device__ __forceinline__ uint32_t pack_h2(float lo, float hi){
    uint32_t d;
    asm("cvt.rn.f16x2.f32 %0, %1, %2;" : "=r"(d) : "f"(hi), "f"(lo));
    return d;
}

__device__ __forceinline__ void mma16(float* c, const uint32_t* a, uint32_t b0, uint32_t b1){
    asm volatile(
        "mma.sync.aligned.m16n8k16.row.col.f32.f16.f16.f32 "
        "{%0,%1,%2,%3}, {%4,%5,%6,%7}, {%8,%9}, {%0,%1,%2,%3};"
        : "+f"(c[0]), "+f"(c[1]), "+f"(c[2]), "+f"(c[3])
        : "r"(a[0]), "r"(a[1]), "r"(a[2]), "r"(a[3]), "r"(b0), "r"(b1));
}

// ---- pre-kernel: permute + fp16-pack W (layout unchanged) ----
__global__ void wperm_kernel(const float* __restrict__ Wm){
    int idx = blockIdx.x * 256 + threadIdx.x;        // 2304 * 128 total
    if (idx >= 2304 * 128) return;
    int row = idx >> 7, kp = idx & 127;
    int cb = row / 72, r = row % 72;
    int ch = r / 9, p = r % 9;
    int n  = 8 * p + ch;
    int cc = kp >> 5, kpl = kp & 31;
    int s = kpl >> 3, kp8 = kpl & 7;
    int col = 2 * (kp8 & 3) + (kp8 >> 2);
    float e = Wm[row * 256 + 2 * kp];
    float o = Wm[row * 256 + 2 * kp + 1];
    g_wperm[((size_t)(cb * 4 + cc) * 72 + n) * 40 + s * 8 + col] = pack_h2(e, o);
}

extern __shared__ float smf[];

__device__ __forceinline__ void stage_wq(int chunk, uint32_t wd, int tidq){
    const uint32_t* wsrc = g_wperm + (size_t)chunk * (72 * 40);
    #pragma unroll
    for (int i = 0; i < 12; ++i) {
        int slot = tidq + 64 * i;                    // 720 x 16B
        if (slot < 720) CPA16(wd + slot * 16, (const void*)(wsrc + slot * 4));
    }
    CP_COMMIT();
}

__global__ __launch_bounds__(256, 1)
void dynf_mma(const float* __restrict__ x, const float* __restrict__ bias,
              float* __restrict__ out)
{
    const uint32_t sx = smem_u32(smf);

    const int tid  = threadIdx.x;
    const int wid  = tid >> 5;
    const int lane = tid & 31;
    const int g = lane >> 2, q = lane & 3;
    const int mhalf   = wid & 1;                     // M base = 64*mhalf
    const int quarter = wid >> 1;                    // 0..3: cb tiles [8q, 8q+8)
    const int tidq = tid & 63;
    const int wb   = mhalf * 64;
    const int h  = blockIdx.x;
    const int bb = blockIdx.y;

    const uint32_t swq = sx + XPBYTES + (uint32_t)quarter * (3u * WCHUNKB);

    // prefetch my quarter's chunk 0 into ring slot 0
    stage_wq(quarter * 32 + 0, swq + 0u * WCHUNKB, tidq);

    // stage X row as packed f16x2 pairs (all 256 threads)
    {
        const float* xsrc = x + (size_t)bb * CN * HW + (size_t)h * WN;
        #pragma unroll 4
        for (int i = 0; i < 16; ++i) {
            int slot = tid + 256 * i;                // 4096: kp(128) x w4(32)
            int kp = slot >> 5, w4 = slot & 31;
            const float4 e = *(const float4*)(xsrc + (size_t)(2 * kp) * HW + w4 * 4);
            const float4 o = *(const float4*)(xsrc + (size_t)(2 * kp + 1) * HW + w4 * 4);
            uint32_t v0 = pack_h2(e.x, o.x), v1 = pack_h2(e.y, o.y);
            uint32_t v2 = pack_h2(e.z, o.z), v3 = pack_h2(e.w, o.w);
            asm volatile("st.shared.v4.b32 [%0], {%1,%2,%3,%4};"
                         :: "r"(sx + (uint32_t)kp * XPROWB + (uint32_t)w4 * 16),
                            "r"(v0), "r"(v1), "r"(v2), "r"(v3) : "memory");
        }
    }
    __syncthreads();                                 // X visible to all quarters

    // ===== per-quarter main loop: 8 cb tiles x 4 k64 chunks x 4 k16 steps =====
    int cur = 0;                                     // ring slot of current chunk
    for (int cbl = 0; cbl < 8; ++cbl) {
        const int cb = quarter * 8 + cbl;
        float acc[9][4][4];                          // [tap j][m16 strip][frag]
        #pragma unroll
        for (int j = 0; j < 9; ++j)
            #pragma unroll
            for (int st = 0; st < 4; ++st)
                #pragma unroll
                for (int e = 0; e < 4; ++e) acc[j][st][e] = 0.f;

        for (int cc = 0; cc < 4; ++cc) {
            const int ci = cbl * 4 + cc;             // 0..31 within quarter
            const int nxt = (cur == 2) ? 0 : cur + 1;
            if (ci + 1 < 32) {
                // slot nxt last read at iter ci-2; barrier at ci-1 separates.
                stage_wq(quarter * 32 + ci + 1, swq + (uint32_t)nxt * WCHUNKB, tidq);
                CP_WAIT(1);                          // chunk ci complete
            } else {
                CP_WAIT(0);
            }
            asm volatile("bar.sync %0, 64;" :: "r"(quarter + 1) : "memory");

            const uint32_t wbf = swq + (uint32_t)cur * WCHUNKB;
            #pragma unroll
            for (int s = 0; s < 4; ++s) {            // k16 steps
                const uint32_t r0 = sx + (uint32_t)(cc * 32 + s * 8 + q) * XPROWB
                                  + (uint32_t)(wb + g) * 4;
                uint32_t a[4][4];
                #pragma unroll
                for (int st = 0; st < 4; ++st) {
                    const uint32_t rs = r0 + (uint32_t)st * 64u;
                    asm volatile("ld.shared.b32 %0, [%1];"      : "=r"(a[st][0]) : "r"(rs));
                    asm volatile("ld.shared.b32 %0, [%1+32];"   : "=r"(a[st][1]) : "r"(rs));
                    asm volatile("ld.shared.b32 %0, [%1+2176];" : "=r"(a[st][2]) : "r"(rs));
                    asm volatile("ld.shared.b32 %0, [%1+2208];" : "=r"(a[st][3]) : "r"(rs));
                }
                #pragma unroll
                for (int j = 0; j < 9; ++j) {
                    uint32_t b0, b1;
                    const uint32_t baddr = wbf + (uint32_t)(8 * j + g) * WROWB
                                         + (uint32_t)(s * 32 + q * 8);
                    asm volatile("ld.shared.v2.b32 {%0,%1}, [%2];"
                                 : "=r"(b0), "=r"(b1) : "r"(baddr));
                    mma16(acc[j][0], a[0], b0, b1);
                    mma16(acc[j][1], a[1], b0, b1);
                    mma16(acc[j][2], a[2], b0, b1);
                    mma16(acc[j][3], a[3], b0, b1);
                }
            }
            cur = nxt;
        }

        // ---- fused 9-tap epilogue: lane (g,q) owns ch 2q,2q+1 at 8 w positions ----
        #pragma unroll
        for (int b2 = 0; b2 < 2; ++b2) {
            const int ch = 2 * q + b2;
            const int c  = cb * 8 + ch;
            const float* xc = x + (size_t)(bb * CN + c) * HW;
            const float* bp = bias + cb * 72 + ch * 9;
            float res[8];
            #pragma unroll
            for (int r = 0; r < 8; ++r) res[r] = 0.f;
            #pragma unroll
            for (int j = 0; j < 9; ++j) {
                const int di = j / 3 - 1, dj = j % 3 - 1;
                const int hh = h + di;
                const bool hok = (hh >= 0) && (hh < HN);
                const float bv = __ldg(bp + j);
                const float* xr = xc + (size_t)hh * WN;
                #pragma unroll
                for (int r = 0; r < 8; ++r) {
                    const int st = r >> 1;
                    const int w  = wb + 16 * st + g + 8 * (r & 1);
                    const int ww = w + dj;
                    const float fv = acc[j][st][(r & 1) ? (2 + b2) : b2];
                    const float xv = (hok && ww >= 0 && ww < WN) ? __ldg(xr + ww) : 0.f;
                    res[r] += (fv + bv) * xv;
                }
            }
            float* orow = out + (size_t)(bb * CN + c) * HW + (size_t)h * WN;
            #pragma unroll
            for (int r = 0; r < 8; ++r) {
                const int st = r >> 1;
                orow[wb + 16 * st + g + 8 * (r & 1)] = res[r];
            }
        }
    }
}

extern "C" void kernel_launch(void* const* d_in, const int* in_sizes, int n_in,
                              void* d_out, int out_size)
{
    const float* x = nullptr; const float* Wm = nullptr; const float* b = nullptr;
    for (int i = 0; i < n_in; ++i) {
        if      (in_sizes[i] == 16777216) x  = (const float*)d_in[i];
        else if (in_sizes[i] == 589824)   Wm = (const float*)d_in[i];
        else if (in_sizes[i] == 2304)     b  = (const float*)d_in[i];
    }
    float* out = (float*)d_out;

    wperm_kernel<<<1152, 256>>>(Wm);

    static int cfg_done = 0;
    if (!cfg_done) {
        cudaFuncSetAttribute(dynf_mma, cudaFuncAttributeMaxDynamicSharedMemorySize,
                             (int)SMEM_TOTAL);
        cfg_done = 1;
    }
    dim3 grid(HN, 4);                 // 512 CTAs: one per (h, b)
    dynf_mma<<<grid, 256, SMEM_TOTAL>>>(x, b, out);
}